// round 5
// baseline (speedup 1.0000x reference)
#include <cuda_runtime.h>
#include <math.h>

#define N_SAMPLES 32768
#define N_CLASSES 1000
#define DIM       1024
#define KNN_K     16

// ---- scratch (small; no allocs allowed) ----
__device__ float g_yy[N_CLASSES];     // |c_j|^2
__device__ float g_cn[N_CLASSES];     // clipped |c_j|
__device__ float g_fn[N_SAMPLES];     // clipped |f_i|
__device__ float g_scores[N_SAMPLES];
__device__ int   g_lab[N_SAMPLES];    // argmax_j cos

__device__ __forceinline__ float warp_sum(float v) {
    #pragma unroll
    for (int o = 16; o; o >>= 1) v += __shfl_xor_sync(0xffffffffu, v, o);
    return v;
}
__device__ __forceinline__ float warp_max(float v) {
    #pragma unroll
    for (int o = 16; o; o >>= 1) v = fmaxf(v, __shfl_xor_sync(0xffffffffu, v, o));
    return v;
}

// ---------------- centroid norms: 1 warp per class ----------------
__global__ void k_cnorm(const float* __restrict__ cent) {
    int w = (blockIdx.x * blockDim.x + threadIdx.x) >> 5;
    int lane = threadIdx.x & 31;
    if (w >= N_CLASSES) return;
    const float4* row = (const float4*)(cent + (size_t)w * DIM);
    float s = 0.f;
    #pragma unroll 4
    for (int j = lane; j < DIM / 4; j += 32) {
        float4 v = row[j];
        s += v.x * v.x + v.y * v.y + v.z * v.z + v.w * v.w;
    }
    s = warp_sum(s);
    if (lane == 0) {
        g_yy[w] = s;
        g_cn[w] = fmaxf(__fsqrt_rn(s), 1e-8f);
    }
}

// ---------------- feature norms: 1 warp per sample ----------------
__global__ void k_fnorm(const float* __restrict__ feat) {
    int w = (blockIdx.x * blockDim.x + threadIdx.x) >> 5;
    int lane = threadIdx.x & 31;
    if (w >= N_SAMPLES) return;
    const float4* row = (const float4*)(feat + (size_t)w * DIM);
    float s = 0.f;
    #pragma unroll 4
    for (int j = lane; j < DIM / 4; j += 32) {
        float4 v = row[j];
        s += v.x * v.x + v.y * v.y + v.z * v.z + v.w * v.w;
    }
    s = warp_sum(s);
    if (lane == 0) g_fn[w] = fmaxf(__fsqrt_rn(s), 1e-8f);
}

// ------------- scores: max softmax prob, 1 warp per sample -------------
__global__ void k_scores(const float* __restrict__ pred) {
    int w = (blockIdx.x * blockDim.x + threadIdx.x) >> 5;
    int lane = threadIdx.x & 31;
    if (w >= N_SAMPLES) return;
    const float4* row = (const float4*)(pred + (size_t)w * N_CLASSES);
    float m = -1e30f;
    #pragma unroll 2
    for (int j = lane; j < N_CLASSES / 4; j += 32) {
        float4 v = row[j];
        m = fmaxf(m, fmaxf(fmaxf(v.x, v.y), fmaxf(v.z, v.w)));
    }
    m = warp_max(m);
    float s = 0.f;
    #pragma unroll 2
    for (int j = lane; j < N_CLASSES / 4; j += 32) {
        float4 v = row[j];
        s += expf(v.x - m) + expf(v.y - m) + expf(v.z - m) + expf(v.w - m);
    }
    s = warp_sum(s);
    if (lane == 0) g_scores[w] = 1.0f / s;
}

// --------- fused cos-GEMM + argmax/argmin (normalize-first, exact fp32) ---------
// Tile: M=128 x N=64, K-chunk 8, double-buffered smem, 256 threads, 8x4 micro-tile.
// Each output accumulates as ONE serial FMA chain with k strictly ascending —
// matching cuBLAS/Triton fp32 accumulation order.
#define MT 128
#define NT 64
#define KT 8

__device__ __forceinline__ float4 scale4(float4 v, float inv) {
    float4 o;
    o.x = v.x * inv; o.y = v.y * inv; o.z = v.z * inv; o.w = v.w * inv;
    return o;
}

__global__ void __launch_bounds__(256, 2)
k_main(const float* __restrict__ feat, const float* __restrict__ cent,
       float* __restrict__ out_label) {
    __shared__ float As[2][KT][MT];
    __shared__ float Bs[2][KT][NT];
    __shared__ float Sdot[MT][NT + 1];
    __shared__ float Syy[NT], Snc[NT];

    const int tid = threadIdx.x;
    const int m0  = blockIdx.x * MT;
    const int tx  = tid & 15;
    const int ty  = tid >> 4;

    float bestCos = -1e30f, bestD = 1e30f;
    int   bestCj = 0, bestDj = 0;
    float nf = 0.f;
    if (tid < MT) nf = g_fn[m0 + tid];

    const int arow = tid >> 1;
    const int ak   = (tid & 1) << 2;
    const float* aptr = feat + (size_t)(m0 + arow) * DIM + ak;
    const float a_inv = 1.0f / g_fn[m0 + arow];     // row-uniform scale: argmax-safe
    const int brow = tid >> 1;                       // valid for tid < 128

    for (int c0 = 0; c0 < N_CLASSES; c0 += NT) {
        float acc[8][4];
        #pragma unroll
        for (int r = 0; r < 8; r++)
            #pragma unroll
            for (int e = 0; e < 4; e++) acc[r][e] = 0.f;

        const bool bvalid = (tid < 128) && (c0 + brow < N_CLASSES);
        const float* bptr = cent + (size_t)(c0 + brow) * DIM + ak;
        const float b_inv = bvalid ? 1.0f / g_cn[c0 + brow] : 0.f;

        if (tid < NT) {
            int j = c0 + tid;
            Syy[tid] = (j < N_CLASSES) ? g_yy[j] : 1e30f;
            Snc[tid] = (j < N_CLASSES) ? g_cn[j] : 0.f;
        }

        {   // prologue: K-chunk 0 into buffer 0 (normalized elements)
            float4 av = scale4(*(const float4*)(aptr), a_inv);
            As[0][ak + 0][arow] = av.x; As[0][ak + 1][arow] = av.y;
            As[0][ak + 2][arow] = av.z; As[0][ak + 3][arow] = av.w;
            if (tid < 128) {
                float4 bv = bvalid ? scale4(*(const float4*)(bptr), b_inv)
                                   : make_float4(0.f, 0.f, 0.f, 0.f);
                Bs[0][ak + 0][brow] = bv.x; Bs[0][ak + 1][brow] = bv.y;
                Bs[0][ak + 2][brow] = bv.z; Bs[0][ak + 3][brow] = bv.w;
            }
        }
        __syncthreads();

        for (int kt = 0; kt < DIM / KT; kt++) {
            const int cur = kt & 1;
            float4 an, bn;
            const bool more = (kt + 1 < DIM / KT);
            if (more) {
                an = scale4(*(const float4*)(aptr + (kt + 1) * KT), a_inv);
                if (tid < 128)
                    bn = bvalid ? scale4(*(const float4*)(bptr + (kt + 1) * KT), b_inv)
                                : make_float4(0.f, 0.f, 0.f, 0.f);
            }
            #pragma unroll
            for (int kk = 0; kk < KT; kk++) {
                float4 a0 = *(const float4*)&As[cur][kk][ty * 8];
                float4 a1 = *(const float4*)&As[cur][kk][ty * 8 + 4];
                float4 b  = *(const float4*)&Bs[cur][kk][tx * 4];
                const float ar[8] = {a0.x, a0.y, a0.z, a0.w, a1.x, a1.y, a1.z, a1.w};
                const float br[4] = {b.x, b.y, b.z, b.w};
                #pragma unroll
                for (int r = 0; r < 8; r++)
                    #pragma unroll
                    for (int e = 0; e < 4; e++)
                        acc[r][e] = fmaf(ar[r], br[e], acc[r][e]);
            }
            if (more) {
                const int nxt = cur ^ 1;
                As[nxt][ak + 0][arow] = an.x; As[nxt][ak + 1][arow] = an.y;
                As[nxt][ak + 2][arow] = an.z; As[nxt][ak + 3][arow] = an.w;
                if (tid < 128) {
                    Bs[nxt][ak + 0][brow] = bn.x; Bs[nxt][ak + 1][brow] = bn.y;
                    Bs[nxt][ak + 2][brow] = bn.z; Bs[nxt][ak + 3][brow] = bn.w;
                }
            }
            __syncthreads();
        }

        #pragma unroll
        for (int r = 0; r < 8; r++)
            #pragma unroll
            for (int e = 0; e < 4; e++)
                Sdot[ty * 8 + r][tx * 4 + e] = acc[r][e];
        __syncthreads();

        if (tid < MT) {
            const int jmax = min(NT, N_CLASSES - c0);
            #pragma unroll 4
            for (int jj = 0; jj < jmax; jj++) {
                float cosv = Sdot[tid][jj];                         // cos similarity
                float dist = Syy[jj] - 2.0f * cosv * nf * Snc[jj];  // euc^2 - |f|^2
                if (cosv > bestCos) { bestCos = cosv; bestCj = c0 + jj; }
                if (dist < bestD)   { bestD = dist;   bestDj = c0 + jj; }
            }
        }
        __syncthreads();
    }

    if (tid < MT) {
        int i = m0 + tid;
        g_lab[i] = bestCj;
        out_label[i] = (bestCj == bestDj && bestCos > 0.85f) ? (float)bestCj : -1.0f;
    }
}

// --------- sequential bounded top-K scatter: 1 warp per class ---------
__global__ void k_scatter(const float* __restrict__ ptn_in,
                          const int*   __restrict__ fidx_in,
                          const int*   __restrict__ uidx,
                          float* __restrict__ out_ptn,
                          float* __restrict__ out_fidx) {
    int w = (blockIdx.x * blockDim.x + threadIdx.x) >> 5;   // class id
    int lane = threadIdx.x & 31;
    if (w >= N_CLASSES) return;

    float p[KNN_K];
    int   fi[KNN_K];
    #pragma unroll
    for (int k = 0; k < KNN_K; k++) {
        p[k]  = __ldg(&ptn_in[w * KNN_K + k]);
        fi[k] = __ldg(&fidx_in[w * KNN_K + k]);
    }

    for (int i0 = 0; i0 < N_SAMPLES; i0 += 32) {
        int li = g_lab[i0 + lane];
        unsigned m = __ballot_sync(0xffffffffu, li == w);
        if (m) {
            float sc = g_scores[i0 + lane];
            int   ui = uidx[i0 + lane];
            while (m) {
                int src = __ffs(m) - 1;
                m &= m - 1;
                float s = __shfl_sync(0xffffffffu, sc, src);
                int   u = __shfl_sync(0xffffffffu, ui, src);
                float mn = p[0]; int mi = 0;
                #pragma unroll
                for (int k = 1; k < KNN_K; k++)
                    if (p[k] < mn) { mn = p[k]; mi = k; }
                if (s > mn) {
                    #pragma unroll
                    for (int k = 0; k < KNN_K; k++)
                        if (k == mi) { p[k] = s; fi[k] = u; }
                }
            }
        }
    }

    if (lane == 0) {
        #pragma unroll
        for (int k = 0; k < KNN_K; k++) {
            out_ptn[w * KNN_K + k]  = p[k];
            out_fidx[w * KNN_K + k] = (float)fi[k];
        }
    }
}

extern "C" void kernel_launch(void* const* d_in, const int* in_sizes, int n_in,
                              void* d_out, int out_size) {
    (void)out_size;
    const float* feature = 0; const float* pred = 0; const int* uidx = 0;
    const float* cent = 0;    const float* ptn_in = 0; const int* fidx_in = 0;
    for (int i = 0; i < n_in; i++) {
        long long s = in_sizes[i];
        if      (s == (long long)N_SAMPLES * DIM)       feature = (const float*)d_in[i];
        else if (s == (long long)N_SAMPLES * N_CLASSES) pred    = (const float*)d_in[i];
        else if (s == (long long)N_CLASSES * DIM)       cent    = (const float*)d_in[i];
        else if (s == N_SAMPLES)                        uidx    = (const int*)d_in[i];
        else if (s == N_CLASSES * KNN_K) {
            if (!ptn_in) ptn_in = (const float*)d_in[i];
            else         fidx_in = (const int*)d_in[i];
        }
    }
    if (!feature) feature = (const float*)d_in[0];
    if (!pred)    pred    = (const float*)d_in[1];
    if (!uidx)    uidx    = (const int*)d_in[2];
    if (!cent)    cent    = (const float*)d_in[3];
    if (!ptn_in)  ptn_in  = (const float*)d_in[4];
    if (!fidx_in) fidx_in = (const int*)d_in[5];

    float* out       = (float*)d_out;
    float* out_label = out;                                 // [N]
    float* out_ptn   = out + N_SAMPLES;                     // [C*KNN]
    float* out_fidx  = out + N_SAMPLES + N_CLASSES * KNN_K; // [C*KNN] (as float)

    k_cnorm <<<125, 256>>>(cent);
    k_fnorm <<<4096, 256>>>(feature);
    k_scores<<<4096, 256>>>(pred);
    k_main  <<<N_SAMPLES / MT, 256>>>(feature, cent, out_label);
    k_scatter<<<125, 256>>>(ptn_in, fidx_in, uidx, out_ptn, out_fidx);
}

// round 7
// speedup vs baseline: 1.0004x; 1.0004x over previous
#include <cuda_runtime.h>
#include <math.h>

#define N_SAMPLES 32768
#define N_CLASSES 1000
#define DIM       1024
#define KNN_K     16

// ---- scratch (small; no allocs allowed) ----
__device__ float g_yy[N_CLASSES];     // |c_j|^2
__device__ float g_cn[N_CLASSES];     // clipped |c_j|
__device__ float g_fn[N_SAMPLES];     // clipped |f_i|
__device__ float g_scores[N_SAMPLES];
__device__ int   g_lab[N_SAMPLES];    // argmax_j cos

__device__ __forceinline__ float warp_sum(float v) {
    #pragma unroll
    for (int o = 16; o; o >>= 1) v += __shfl_xor_sync(0xffffffffu, v, o);
    return v;
}
__device__ __forceinline__ float warp_max(float v) {
    #pragma unroll
    for (int o = 16; o; o >>= 1) v = fmaxf(v, __shfl_xor_sync(0xffffffffu, v, o));
    return v;
}

// ---------------- centroid norms: 1 warp per class ----------------
__global__ void k_cnorm(const float* __restrict__ cent) {
    int w = (blockIdx.x * blockDim.x + threadIdx.x) >> 5;
    int lane = threadIdx.x & 31;
    if (w >= N_CLASSES) return;
    const float4* row = (const float4*)(cent + (size_t)w * DIM);
    float s = 0.f;
    #pragma unroll 4
    for (int j = lane; j < DIM / 4; j += 32) {
        float4 v = row[j];
        s += v.x * v.x + v.y * v.y + v.z * v.z + v.w * v.w;
    }
    s = warp_sum(s);
    if (lane == 0) {
        g_yy[w] = s;
        g_cn[w] = fmaxf(__fsqrt_rn(s), 1e-8f);
    }
}

// ---------------- feature norms: 1 warp per sample ----------------
__global__ void k_fnorm(const float* __restrict__ feat) {
    int w = (blockIdx.x * blockDim.x + threadIdx.x) >> 5;
    int lane = threadIdx.x & 31;
    if (w >= N_SAMPLES) return;
    const float4* row = (const float4*)(feat + (size_t)w * DIM);
    float s = 0.f;
    #pragma unroll 4
    for (int j = lane; j < DIM / 4; j += 32) {
        float4 v = row[j];
        s += v.x * v.x + v.y * v.y + v.z * v.z + v.w * v.w;
    }
    s = warp_sum(s);
    if (lane == 0) g_fn[w] = fmaxf(__fsqrt_rn(s), 1e-8f);
}

// ------------- scores: max softmax prob, 1 warp per sample -------------
__global__ void k_scores(const float* __restrict__ pred) {
    int w = (blockIdx.x * blockDim.x + threadIdx.x) >> 5;
    int lane = threadIdx.x & 31;
    if (w >= N_SAMPLES) return;
    const float4* row = (const float4*)(pred + (size_t)w * N_CLASSES);
    float m = -1e30f;
    #pragma unroll 2
    for (int j = lane; j < N_CLASSES / 4; j += 32) {
        float4 v = row[j];
        m = fmaxf(m, fmaxf(fmaxf(v.x, v.y), fmaxf(v.z, v.w)));
    }
    m = warp_max(m);
    float s = 0.f;
    #pragma unroll 2
    for (int j = lane; j < N_CLASSES / 4; j += 32) {
        float4 v = row[j];
        s += expf(v.x - m) + expf(v.y - m) + expf(v.z - m) + expf(v.w - m);
    }
    s = warp_sum(s);
    if (lane == 0) g_scores[w] = 1.0f / s;
}

// --------- fused cos-GEMM + argmax/argmin (normalize-first, exact fp32) ---------
// Tile: M=128 x N=64, K-chunk 8, double-buffered smem, 256 threads, 8x4 micro-tile.
// Each output accumulates as ONE serial FMA chain with k strictly ascending —
// matching cuBLAS/Triton fp32 accumulation order.
#define MT 128
#define NT 64
#define KT 8

__device__ __forceinline__ float4 scale4(float4 v, float inv) {
    float4 o;
    o.x = v.x * inv; o.y = v.y * inv; o.z = v.z * inv; o.w = v.w * inv;
    return o;
}

__global__ void __launch_bounds__(256, 2)
k_main(const float* __restrict__ feat, const float* __restrict__ cent,
       float* __restrict__ out_label) {
    __shared__ float As[2][KT][MT];
    __shared__ float Bs[2][KT][NT];
    __shared__ float Sdot[MT][NT + 1];
    __shared__ float Syy[NT], Snc[NT];

    const int tid = threadIdx.x;
    const int m0  = blockIdx.x * MT;
    const int tx  = tid & 15;
    const int ty  = tid >> 4;

    float bestCos = -1e30f, bestD = 1e30f;
    int   bestCj = 0, bestDj = 0;
    float nf = 0.f;
    if (tid < MT) nf = g_fn[m0 + tid];

    const int arow = tid >> 1;
    const int ak   = (tid & 1) << 2;
    const float* aptr = feat + (size_t)(m0 + arow) * DIM + ak;
    const float a_inv = 1.0f / g_fn[m0 + arow];     // row-uniform scale: argmax-safe
    const int brow = tid >> 1;                       // valid for tid < 128

    for (int c0 = 0; c0 < N_CLASSES; c0 += NT) {
        float acc[8][4];
        #pragma unroll
        for (int r = 0; r < 8; r++)
            #pragma unroll
            for (int e = 0; e < 4; e++) acc[r][e] = 0.f;

        const bool bvalid = (tid < 128) && (c0 + brow < N_CLASSES);
        const float* bptr = cent + (size_t)(c0 + brow) * DIM + ak;
        const float b_inv = bvalid ? 1.0f / g_cn[c0 + brow] : 0.f;

        if (tid < NT) {
            int j = c0 + tid;
            Syy[tid] = (j < N_CLASSES) ? g_yy[j] : 1e30f;
            Snc[tid] = (j < N_CLASSES) ? g_cn[j] : 0.f;
        }

        {   // prologue: K-chunk 0 into buffer 0 (normalized elements)
            float4 av = scale4(*(const float4*)(aptr), a_inv);
            As[0][ak + 0][arow] = av.x; As[0][ak + 1][arow] = av.y;
            As[0][ak + 2][arow] = av.z; As[0][ak + 3][arow] = av.w;
            if (tid < 128) {
                float4 bv = bvalid ? scale4(*(const float4*)(bptr), b_inv)
                                   : make_float4(0.f, 0.f, 0.f, 0.f);
                Bs[0][ak + 0][brow] = bv.x; Bs[0][ak + 1][brow] = bv.y;
                Bs[0][ak + 2][brow] = bv.z; Bs[0][ak + 3][brow] = bv.w;
            }
        }
        __syncthreads();

        for (int kt = 0; kt < DIM / KT; kt++) {
            const int cur = kt & 1;
            float4 an, bn;
            const bool more = (kt + 1 < DIM / KT);
            if (more) {
                an = scale4(*(const float4*)(aptr + (kt + 1) * KT), a_inv);
                if (tid < 128)
                    bn = bvalid ? scale4(*(const float4*)(bptr + (kt + 1) * KT), b_inv)
                                : make_float4(0.f, 0.f, 0.f, 0.f);
            }
            #pragma unroll
            for (int kk = 0; kk < KT; kk++) {
                float4 a0 = *(const float4*)&As[cur][kk][ty * 8];
                float4 a1 = *(const float4*)&As[cur][kk][ty * 8 + 4];
                float4 b  = *(const float4*)&Bs[cur][kk][tx * 4];
                const float ar[8] = {a0.x, a0.y, a0.z, a0.w, a1.x, a1.y, a1.z, a1.w};
                const float br[4] = {b.x, b.y, b.z, b.w};
                #pragma unroll
                for (int r = 0; r < 8; r++)
                    #pragma unroll
                    for (int e = 0; e < 4; e++)
                        acc[r][e] = fmaf(ar[r], br[e], acc[r][e]);
            }
            if (more) {
                const int nxt = cur ^ 1;
                As[nxt][ak + 0][arow] = an.x; As[nxt][ak + 1][arow] = an.y;
                As[nxt][ak + 2][arow] = an.z; As[nxt][ak + 3][arow] = an.w;
                if (tid < 128) {
                    Bs[nxt][ak + 0][brow] = bn.x; Bs[nxt][ak + 1][brow] = bn.y;
                    Bs[nxt][ak + 2][brow] = bn.z; Bs[nxt][ak + 3][brow] = bn.w;
                }
            }
            __syncthreads();
        }

        #pragma unroll
        for (int r = 0; r < 8; r++)
            #pragma unroll
            for (int e = 0; e < 4; e++)
                Sdot[ty * 8 + r][tx * 4 + e] = acc[r][e];
        __syncthreads();

        if (tid < MT) {
            const int jmax = min(NT, N_CLASSES - c0);
            #pragma unroll 4
            for (int jj = 0; jj < jmax; jj++) {
                float cosv = Sdot[tid][jj];                         // cos similarity
                float dist = Syy[jj] - 2.0f * cosv * nf * Snc[jj];  // euc^2 - |f|^2
                if (cosv > bestCos) { bestCos = cosv; bestCj = c0 + jj; }
                if (dist < bestD)   { bestD = dist;   bestDj = c0 + jj; }
            }
        }
        __syncthreads();
    }

    if (tid < MT) {
        int i = m0 + tid;
        g_lab[i] = bestCj;
        out_label[i] = (bestCj == bestDj && bestCos > 0.85f) ? (float)bestCj : -1.0f;
    }
}

// --------- sequential bounded top-K scatter: 1 warp per class ---------
__global__ void k_scatter(const float* __restrict__ ptn_in,
                          const int*   __restrict__ fidx_in,
                          const int*   __restrict__ uidx,
                          float* __restrict__ out_ptn,
                          float* __restrict__ out_fidx) {
    int w = (blockIdx.x * blockDim.x + threadIdx.x) >> 5;   // class id
    int lane = threadIdx.x & 31;
    if (w >= N_CLASSES) return;

    float p[KNN_K];
    int   fi[KNN_K];
    #pragma unroll
    for (int k = 0; k < KNN_K; k++) {
        p[k]  = __ldg(&ptn_in[w * KNN_K + k]);
        fi[k] = __ldg(&fidx_in[w * KNN_K + k]);
    }

    for (int i0 = 0; i0 < N_SAMPLES; i0 += 32) {
        int li = g_lab[i0 + lane];
        unsigned m = __ballot_sync(0xffffffffu, li == w);
        if (m) {
            float sc = g_scores[i0 + lane];
            int   ui = uidx[i0 + lane];
            while (m) {
                int src = __ffs(m) - 1;
                m &= m - 1;
                float s = __shfl_sync(0xffffffffu, sc, src);
                int   u = __shfl_sync(0xffffffffu, ui, src);
                float mn = p[0]; int mi = 0;
                #pragma unroll
                for (int k = 1; k < KNN_K; k++)
                    if (p[k] < mn) { mn = p[k]; mi = k; }
                if (s > mn) {
                    #pragma unroll
                    for (int k = 0; k < KNN_K; k++)
                        if (k == mi) { p[k] = s; fi[k] = u; }
                }
            }
        }
    }

    if (lane == 0) {
        #pragma unroll
        for (int k = 0; k < KNN_K; k++) {
            out_ptn[w * KNN_K + k]  = p[k];
            out_fidx[w * KNN_K + k] = (float)fi[k];
        }
    }
}

extern "C" void kernel_launch(void* const* d_in, const int* in_sizes, int n_in,
                              void* d_out, int out_size) {
    (void)out_size;
    const float* feature = 0; const float* pred = 0; const int* uidx = 0;
    const float* cent = 0;    const float* ptn_in = 0; const int* fidx_in = 0;
    for (int i = 0; i < n_in; i++) {
        long long s = in_sizes[i];
        if      (s == (long long)N_SAMPLES * DIM)       feature = (const float*)d_in[i];
        else if (s == (long long)N_SAMPLES * N_CLASSES) pred    = (const float*)d_in[i];
        else if (s == (long long)N_CLASSES * DIM)       cent    = (const float*)d_in[i];
        else if (s == N_SAMPLES)                        uidx    = (const int*)d_in[i];
        else if (s == N_CLASSES * KNN_K) {
            if (!ptn_in) ptn_in = (const float*)d_in[i];
            else         fidx_in = (const int*)d_in[i];
        }
    }
    if (!feature) feature = (const float*)d_in[0];
    if (!pred)    pred    = (const float*)d_in[1];
    if (!uidx)    uidx    = (const int*)d_in[2];
    if (!cent)    cent    = (const float*)d_in[3];
    if (!ptn_in)  ptn_in  = (const float*)d_in[4];
    if (!fidx_in) fidx_in = (const int*)d_in[5];

    float* out       = (float*)d_out;
    float* out_label = out;                                 // [N]
    float* out_ptn   = out + N_SAMPLES;                     // [C*KNN]
    float* out_fidx  = out + N_SAMPLES + N_CLASSES * KNN_K; // [C*KNN] (as float)

    k_cnorm <<<125, 256>>>(cent);
    k_fnorm <<<4096, 256>>>(feature);
    k_scores<<<4096, 256>>>(pred);
    k_main  <<<N_SAMPLES / MT, 256>>>(feature, cent, out_label);
    k_scatter<<<125, 256>>>(ptn_in, fidx_in, uidx, out_ptn, out_fidx);
}